// round 11
// baseline (speedup 1.0000x reference)
#include <cuda_runtime.h>
#include <cstdint>

#define BATCH 4
#define NPTS  4096
#define FIN   64
#define FOUT  64
#define KNN   20
#define TOTAL (BATCH * NPTS)   // 16384 points

// ---------------- scratch (static device memory; no allocations) ----------------
__device__ float g_key[(size_t)TOTAL * NPTS];   // 268 MB ranking keys
__device__ float g_xT[BATCH * FIN * NPTS];      // x transposed: [b][f][n]
__device__ float g_u[TOTAL * FOUT];             // (W1-W2)x + b
__device__ float g_v[TOTAL * FOUT];             // W2 x
__device__ float g_xs[TOTAL];                   // squared norms
__device__ int   g_idx[TOTAL * KNN];            // knn indices (local to batch)

// ---------------- kernel A: per-point transform (+ writes transposed x) ----------------
__global__ void transform_kernel(const float* __restrict__ x,
                                 const float* __restrict__ W,
                                 const float* __restrict__ bias) {
    __shared__ float Ws[FOUT * 2 * FIN];
    __shared__ float bs[FOUT];
    int t = threadIdx.x;
    for (int i = t; i < FOUT * 2 * FIN; i += blockDim.x) Ws[i] = W[i];
    if (t < FOUT) bs[t] = bias[t];
    __syncthreads();

    int p = blockIdx.x * blockDim.x + t;
    float xr[FIN];
    const float4* xp = (const float4*)(x + (size_t)p * FIN);
#pragma unroll
    for (int q = 0; q < FIN / 4; q++) {
        float4 v4 = xp[q];
        xr[4*q+0] = v4.x; xr[4*q+1] = v4.y; xr[4*q+2] = v4.z; xr[4*q+3] = v4.w;
    }
    float s = 0.f;
#pragma unroll
    for (int c = 0; c < FIN; c++) s += xr[c] * xr[c];
    g_xs[p] = s;

    float* xt = g_xT + (size_t)(p >> 12) * FIN * NPTS + (p & (NPTS - 1));
#pragma unroll
    for (int c = 0; c < FIN; c++) xt[(size_t)c * NPTS] = xr[c];

    for (int o = 0; o < FOUT; o++) {
        float a1 = 0.f, a2 = 0.f;
        const float* wrow = &Ws[o * 2 * FIN];
#pragma unroll
        for (int c = 0; c < FIN; c++) {
            a1 += xr[c] * wrow[c];
            a2 += xr[c] * wrow[FIN + c];
        }
        g_u[p * FOUT + o] = a1 - a2 + bs[o];
        g_v[p * FOUT + o] = a2;
    }
}

// ---------------- kernel B: symmetric Gram + ranking keys (unchanged from R10) ----------------
#define TILE 128
#define SSTR 132
#define DIST_SMEM (2 * FIN * SSTR * 4)   // 67584 bytes

__global__ __launch_bounds__(256) void dist_kernel(int b) {
    extern __shared__ float sm[];
    float* At = sm;
    float* Bt = sm + FIN * SSTR;

    int id = blockIdx.x;            // upper-tri (by,bx), bx >= by
    int by = 0, rem = id;
    while (rem >= 32 - by) { rem -= 32 - by; by++; }
    int bx = by + rem;

    const float* XT = g_xT + (size_t)b * FIN * NPTS;
    int row0 = by * TILE, col0 = bx * TILE;
    int t  = threadIdx.x;
    int tr = t >> 4, tc = t & 15;

    for (int q = t; q < FIN * 32; q += 256) {
        int f  = q >> 5;
        int rc = (q & 31) * 4;
        *(float4*)&At[f * SSTR + rc] = *(const float4*)(XT + (size_t)f * NPTS + row0 + rc);
        *(float4*)&Bt[f * SSTR + rc] = *(const float4*)(XT + (size_t)f * NPTS + col0 + rc);
    }
    __syncthreads();

    float acc[8][8];
#pragma unroll
    for (int i = 0; i < 8; i++)
#pragma unroll
        for (int j = 0; j < 8; j++) acc[i][j] = 0.f;

    const float* Ar = At + tr * 8;
    const float* Br = Bt + tc * 4;
#pragma unroll 4
    for (int f = 0; f < FIN; f++) {
        float4 a0 = *(const float4*)(Ar + f * SSTR);
        float4 a1 = *(const float4*)(Ar + f * SSTR + 4);
        float4 b0 = *(const float4*)(Br + f * SSTR);
        float4 b1 = *(const float4*)(Br + f * SSTR + 64);
        float av[8] = {a0.x,a0.y,a0.z,a0.w,a1.x,a1.y,a1.z,a1.w};
        float bv[8] = {b0.x,b0.y,b0.z,b0.w,b1.x,b1.y,b1.z,b1.w};
#pragma unroll
        for (int i = 0; i < 8; i++)
#pragma unroll
            for (int j = 0; j < 8; j++)
                acc[i][j] = fmaf(av[i], bv[j], acc[i][j]);
    }

    int colG[8];
#pragma unroll
    for (int j = 0; j < 4; j++) { colG[j] = col0 + tc * 4 + j; colG[j+4] = col0 + 64 + tc * 4 + j; }

    float xsr[8], xsc[8];
#pragma unroll
    for (int i = 0; i < 8; i++) xsr[i] = g_xs[b * NPTS + row0 + tr * 8 + i];
#pragma unroll
    for (int j = 0; j < 8; j++) xsc[j] = g_xs[b * NPTS + colG[j]];

#pragma unroll
    for (int i = 0; i < 8; i++) {
        size_t base = (size_t)(b * NPTS + row0 + tr * 8 + i) * NPTS;
        float4 o0 = make_float4(xsc[0] - 2.f*acc[i][0], xsc[1] - 2.f*acc[i][1],
                                xsc[2] - 2.f*acc[i][2], xsc[3] - 2.f*acc[i][3]);
        float4 o1 = make_float4(xsc[4] - 2.f*acc[i][4], xsc[5] - 2.f*acc[i][5],
                                xsc[6] - 2.f*acc[i][6], xsc[7] - 2.f*acc[i][7]);
        __stcs((float4*)&g_key[base + col0 + tc * 4],      o0);
        __stcs((float4*)&g_key[base + col0 + 64 + tc * 4], o1);
    }
    if (bx != by) {
#pragma unroll
        for (int j = 0; j < 8; j++) {
            size_t base = (size_t)(b * NPTS + colG[j]) * NPTS + row0 + tr * 8;
            float4 m0 = make_float4(xsr[0] - 2.f*acc[0][j], xsr[1] - 2.f*acc[1][j],
                                    xsr[2] - 2.f*acc[2][j], xsr[3] - 2.f*acc[3][j]);
            float4 m1 = make_float4(xsr[4] - 2.f*acc[4][j], xsr[5] - 2.f*acc[5][j],
                                    xsr[6] - 2.f*acc[6][j], xsr[7] - 2.f*acc[7][j]);
            __stcs((float4*)&g_key[base],     m0);
            __stcs((float4*)&g_key[base + 4], m1);
        }
    }
}

// ---------------- kernel C: 2-pass radix + survivor compaction ----------------
// Output SET must equal stable-argsort top-KNN: all keys below theta-bin,
// plus (value, index)-lexicographic smallest within the bin. Order in g_idx
// is irrelevant (gather takes max over the set).
__global__ __launch_bounds__(256) void select_kernel(int b) {
    int iLocal = blockIdx.x;
    int row = b * NPTS + iLocal;
    const float4* keys = (const float4*)(g_key + (size_t)row * NPTS);
    int t = threadIdx.x;

    unsigned v[16];
#pragma unroll
    for (int i2 = 0; i2 < 4; i2++) {
        int f4 = t + i2 * 256;
        float4 kv = __ldcs(&keys[f4]);
        float vv[4] = {kv.x, kv.y, kv.z, kv.w};
        int j0 = f4 * 4;
#pragma unroll
        for (int e = 0; e < 4; e++) {
            unsigned u = __float_as_uint(vv[e]);
            u = (u & 0x80000000u) ? ~u : (u | 0x80000000u);
            v[i2 * 4 + e] = (j0 + e == iLocal) ? 0xFFFFFFFFu : u;
        }
    }

    __shared__ int hist[256];
    __shared__ int sD, sCb, sNeed;
    __shared__ int cnt1, cntT;
    __shared__ unsigned tieb[256];

    unsigned prefix = 0, pmask = 0;
    if (t == 0) sNeed = KNN;

    // passes 0,1: bits [31:24], [23:16]
    for (int pass = 0; pass < 2; pass++) {
        int shift = 24 - 8 * pass;
        hist[t] = 0;
        __syncthreads();
#pragma unroll
        for (int q = 0; q < 16; q++) {
            bool ok = (v[q] & pmask) == prefix;
            unsigned act = __ballot_sync(0xffffffffu, ok);
            if (ok) {
                unsigned d = (v[q] >> shift) & 255u;
                unsigned m = __match_any_sync(act, d);
                if ((t & 31) == (__ffs(m) - 1))
                    atomicAdd(&hist[d], __popc(m));
            }
        }
        __syncthreads();
        if (t < 32) {
            int s[8], tot = 0, base = t * 8;
#pragma unroll
            for (int q2 = 0; q2 < 8; q2++) { s[q2] = hist[base + q2]; tot += s[q2]; }
            int inc = tot;
#pragma unroll
            for (int off = 1; off < 32; off <<= 1) {
                int o = __shfl_up_sync(0xffffffffu, inc, off);
                if (t >= off) inc += o;
            }
            int ex = inc - tot;
            int nd = sNeed;
            if (ex < nd && nd <= inc) {
                int run = ex;
#pragma unroll
                for (int q2 = 0; q2 < 8; q2++) {
                    if (nd <= run + s[q2]) { sD = base + q2; sCb = run; break; }
                    run += s[q2];
                }
            }
        }
        __syncthreads();
        prefix |= ((unsigned)sD) << shift;
        pmask  |= 0xFFu << shift;
        if (t == 0) sNeed -= sCb;
    }

    // collect: below-bin -> direct output; in-bin -> packed (low16<<12)|idx
    if (t == 0) { cnt1 = 0; cntT = 0; }
    __syncthreads();
    unsigned thetaHi = prefix >> 16;
    int* outp = g_idx + row * KNN;
#pragma unroll
    for (int q = 0; q < 16; q++) {
        int j = (t + (q >> 2) * 256) * 4 + (q & 3);
        unsigned hi = v[q] >> 16;
        if (hi < thetaHi)       { int s2 = atomicAdd(&cnt1, 1); outp[s2] = j; }
        else if (hi == thetaHi) {
            int s2 = atomicAdd(&cntT, 1);
            if (s2 < 256) tieb[s2] = ((v[q] & 0xFFFFu) << 12) | (unsigned)j;
        }
    }
    __syncthreads();
    int nTie  = cntT;
    int needF = sNeed;   // cnt1 == KNN - needF by construction

    if (nTie <= 256) {
        // fast path: warp 0 iteratively picks needF smallest packed (value,idx)
        if (t < 32) {
            unsigned c[8];
#pragma unroll
            for (int i = 0; i < 8; i++) {
                int ix = t + i * 32;
                c[i] = (ix < nTie) ? tieb[ix] : 0xFFFFFFFFu;
            }
            int c1 = cnt1;
            for (int s2 = 0; s2 < needF; s2++) {
                unsigned m = 0xFFFFFFFFu;
#pragma unroll
                for (int i = 0; i < 8; i++) m = (c[i] < m) ? c[i] : m;
                unsigned r = m;
#pragma unroll
                for (int off = 16; off; off >>= 1) {
                    unsigned o = __shfl_xor_sync(0xffffffffu, r, off);
                    r = (o < r) ? o : r;
                }
                if (t == 0) outp[c1 + s2] = (int)(r & 0xFFFu);
#pragma unroll
                for (int i = 0; i < 8; i++) if (c[i] == r) c[i] = 0xFFFFFFFFu;
            }
        }
    } else {
        // slow path (pathological tie mass): finish passes 2,3 then exact collect
        for (int pass = 2; pass < 4; pass++) {
            int shift = 24 - 8 * pass;
            hist[t] = 0;
            __syncthreads();
#pragma unroll
            for (int q = 0; q < 16; q++) {
                bool ok = (v[q] & pmask) == prefix;
                unsigned act = __ballot_sync(0xffffffffu, ok);
                if (ok) {
                    unsigned d = (v[q] >> shift) & 255u;
                    unsigned m = __match_any_sync(act, d);
                    if ((t & 31) == (__ffs(m) - 1))
                        atomicAdd(&hist[d], __popc(m));
                }
            }
            __syncthreads();
            if (t < 32) {
                int s[8], tot = 0, base = t * 8;
#pragma unroll
                for (int q2 = 0; q2 < 8; q2++) { s[q2] = hist[base + q2]; tot += s[q2]; }
                int inc = tot;
#pragma unroll
                for (int off = 1; off < 32; off <<= 1) {
                    int o = __shfl_up_sync(0xffffffffu, inc, off);
                    if (t >= off) inc += o;
                }
                int ex = inc - tot;
                int nd = sNeed;
                if (ex < nd && nd <= inc) {
                    int run = ex;
#pragma unroll
                    for (int q2 = 0; q2 < 8; q2++) {
                        if (nd <= run + s[q2]) { sD = base + q2; sCb = run; break; }
                        run += s[q2];
                    }
                }
            }
            __syncthreads();
            prefix |= ((unsigned)sD) << shift;
            pmask  |= 0xFFu << shift;
            if (t == 0) sNeed -= sCb;
        }
        if (t == 0) { cnt1 = 0; cntT = 0; }
        __syncthreads();
        unsigned theta = prefix;
#pragma unroll
        for (int q = 0; q < 16; q++) {
            int j = (t + (q >> 2) * 256) * 4 + (q & 3);
            if (v[q] < theta)       { int s2 = atomicAdd(&cnt1, 1); outp[s2] = j; }
            else if (v[q] == theta) { int s2 = atomicAdd(&cntT, 1); if (s2 < 256) tieb[s2] = (unsigned)j; }
        }
        __syncthreads();
        if (t == 0) {
            int nt = cntT < 256 ? cntT : 256;
            int nf = sNeed, c1 = cnt1;
            for (int s2 = 0; s2 < nf; s2++) {
                unsigned bi = 0, bv2 = 0xFFFFFFFFu;
                for (int q = 0; q < nt; q++) if (tieb[q] < bv2) { bv2 = tieb[q]; bi = q; }
                tieb[bi] = 0xFFFFFFFFu;
                outp[c1 + s2] = (int)bv2;
            }
        }
    }
}

// ---------------- kernel D: gather-max epilogue ----------------
__global__ void gather_kernel(float* __restrict__ out) {
    int gid = blockIdx.x * blockDim.x + threadIdx.x;
    int p = gid >> 6;
    int o = gid & 63;
    int bbase = p & ~(NPTS - 1);
    const int* ip = g_idx + p * KNN;
    float m = -3.402823466e38f;
#pragma unroll
    for (int q = 0; q < KNN; q++) {
        int j = ip[q];
        m = fmaxf(m, g_v[(size_t)(bbase + j) * FOUT + o]);
    }
    out[gid] = g_u[gid] + m;
}

// ---------------- launch: per-batch dist/select pipeline, fork-join streams ----------------
extern "C" void kernel_launch(void* const* d_in, const int* in_sizes, int n_in,
                              void* d_out, int out_size) {
    const float* x    = (const float*)d_in[0];
    const float* W    = (const float*)d_in[1];
    const float* bias = (const float*)d_in[2];
    float* out = (float*)d_out;

    static cudaStream_t s_sel = nullptr;
    static cudaEvent_t  s_evD[BATCH];
    static cudaEvent_t  s_evJoin;
    if (s_sel == nullptr) {
        cudaStreamCreateWithFlags(&s_sel, cudaStreamNonBlocking);
        for (int i = 0; i < BATCH; i++)
            cudaEventCreateWithFlags(&s_evD[i], cudaEventDisableTiming);
        cudaEventCreateWithFlags(&s_evJoin, cudaEventDisableTiming);
        cudaFuncSetAttribute(dist_kernel,
                             cudaFuncAttributeMaxDynamicSharedMemorySize, DIST_SMEM);
    }

    transform_kernel<<<TOTAL / 128, 128>>>(x, W, bias);
    for (int b = 0; b < BATCH; b++) {
        dist_kernel<<<528, 256, DIST_SMEM>>>(b);
        cudaEventRecord(s_evD[b], 0);
        cudaStreamWaitEvent(s_sel, s_evD[b], 0);
        select_kernel<<<NPTS, 256, 0, s_sel>>>(b);
    }
    cudaEventRecord(s_evJoin, s_sel);
    cudaStreamWaitEvent(0, s_evJoin, 0);
    gather_kernel<<<(TOTAL * FOUT) / 256, 256>>>(out);
}

// round 13
// speedup vs baseline: 1.7371x; 1.7371x over previous
#include <cuda_runtime.h>
#include <cstdint>

#define BATCH 4
#define NPTS  4096
#define FIN   64
#define FOUT  64
#define KNN   20
#define TOTAL (BATCH * NPTS)   // 16384 points

// ---------------- scratch (static device memory; no allocations) ----------------
__device__ float g_key[(size_t)TOTAL * NPTS];   // 268 MB ranking keys
__device__ float g_xT[BATCH * FIN * NPTS];      // x transposed: [b][f][n]
__device__ float g_u[TOTAL * FOUT];             // (W1-W2)x + b
__device__ float g_v[TOTAL * FOUT];             // W2 x
__device__ float g_xs[TOTAL];                   // squared norms
__device__ int   g_idx[TOTAL * KNN];            // knn indices (local to batch)

// ---------------- kernel A: per-point transform (+ writes transposed x) ----------------
__global__ void transform_kernel(const float* __restrict__ x,
                                 const float* __restrict__ W,
                                 const float* __restrict__ bias) {
    __shared__ float Ws[FOUT * 2 * FIN];
    __shared__ float bs[FOUT];
    int t = threadIdx.x;
    for (int i = t; i < FOUT * 2 * FIN; i += blockDim.x) Ws[i] = W[i];
    if (t < FOUT) bs[t] = bias[t];
    __syncthreads();

    int p = blockIdx.x * blockDim.x + t;
    float xr[FIN];
    const float4* xp = (const float4*)(x + (size_t)p * FIN);
#pragma unroll
    for (int q = 0; q < FIN / 4; q++) {
        float4 v4 = xp[q];
        xr[4*q+0] = v4.x; xr[4*q+1] = v4.y; xr[4*q+2] = v4.z; xr[4*q+3] = v4.w;
    }
    float s = 0.f;
#pragma unroll
    for (int c = 0; c < FIN; c++) s += xr[c] * xr[c];
    g_xs[p] = s;

    float* xt = g_xT + (size_t)(p >> 12) * FIN * NPTS + (p & (NPTS - 1));
#pragma unroll
    for (int c = 0; c < FIN; c++) xt[(size_t)c * NPTS] = xr[c];

    for (int o = 0; o < FOUT; o++) {
        float a1 = 0.f, a2 = 0.f;
        const float* wrow = &Ws[o * 2 * FIN];
#pragma unroll
        for (int c = 0; c < FIN; c++) {
            a1 += xr[c] * wrow[c];
            a2 += xr[c] * wrow[FIN + c];
        }
        g_u[p * FOUT + o] = a1 - a2 + bs[o];
        g_v[p * FOUT + o] = a2;
    }
}

// ---------------- kernel B: symmetric Gram + ranking keys ----------------
#define TILE 128
#define SSTR 132
#define DIST_SMEM (2 * FIN * SSTR * 4)   // 67584 bytes

__global__ __launch_bounds__(256) void dist_kernel() {
    extern __shared__ float sm[];
    float* At = sm;
    float* Bt = sm + FIN * SSTR;

    int b = blockIdx.z;
    int id = blockIdx.x;            // upper-tri (by,bx), bx >= by
    int by = 0, rem = id;
    while (rem >= 32 - by) { rem -= 32 - by; by++; }
    int bx = by + rem;

    const float* XT = g_xT + (size_t)b * FIN * NPTS;
    int row0 = by * TILE, col0 = bx * TILE;
    int t  = threadIdx.x;
    int tr = t >> 4, tc = t & 15;

    for (int q = t; q < FIN * 32; q += 256) {
        int f  = q >> 5;
        int rc = (q & 31) * 4;
        *(float4*)&At[f * SSTR + rc] = *(const float4*)(XT + (size_t)f * NPTS + row0 + rc);
        *(float4*)&Bt[f * SSTR + rc] = *(const float4*)(XT + (size_t)f * NPTS + col0 + rc);
    }
    __syncthreads();

    float acc[8][8];
#pragma unroll
    for (int i = 0; i < 8; i++)
#pragma unroll
        for (int j = 0; j < 8; j++) acc[i][j] = 0.f;

    const float* Ar = At + tr * 8;
    const float* Br = Bt + tc * 4;
#pragma unroll 4
    for (int f = 0; f < FIN; f++) {
        float4 a0 = *(const float4*)(Ar + f * SSTR);
        float4 a1 = *(const float4*)(Ar + f * SSTR + 4);
        float4 b0 = *(const float4*)(Br + f * SSTR);
        float4 b1 = *(const float4*)(Br + f * SSTR + 64);
        float av[8] = {a0.x,a0.y,a0.z,a0.w,a1.x,a1.y,a1.z,a1.w};
        float bv[8] = {b0.x,b0.y,b0.z,b0.w,b1.x,b1.y,b1.z,b1.w};
#pragma unroll
        for (int i = 0; i < 8; i++)
#pragma unroll
            for (int j = 0; j < 8; j++)
                acc[i][j] = fmaf(av[i], bv[j], acc[i][j]);
    }

    int colG[8];
#pragma unroll
    for (int j = 0; j < 4; j++) { colG[j] = col0 + tc * 4 + j; colG[j+4] = col0 + 64 + tc * 4 + j; }

    float xsr[8], xsc[8];
#pragma unroll
    for (int i = 0; i < 8; i++) xsr[i] = g_xs[b * NPTS + row0 + tr * 8 + i];
#pragma unroll
    for (int j = 0; j < 8; j++) xsc[j] = g_xs[b * NPTS + colG[j]];

#pragma unroll
    for (int i = 0; i < 8; i++) {
        size_t base = (size_t)(b * NPTS + row0 + tr * 8 + i) * NPTS;
        float4 o0 = make_float4(xsc[0] - 2.f*acc[i][0], xsc[1] - 2.f*acc[i][1],
                                xsc[2] - 2.f*acc[i][2], xsc[3] - 2.f*acc[i][3]);
        float4 o1 = make_float4(xsc[4] - 2.f*acc[i][4], xsc[5] - 2.f*acc[i][5],
                                xsc[6] - 2.f*acc[i][6], xsc[7] - 2.f*acc[i][7]);
        __stcs((float4*)&g_key[base + col0 + tc * 4],      o0);
        __stcs((float4*)&g_key[base + col0 + 64 + tc * 4], o1);
    }
    if (bx != by) {
#pragma unroll
        for (int j = 0; j < 8; j++) {
            size_t base = (size_t)(b * NPTS + colG[j]) * NPTS + row0 + tr * 8;
            float4 m0 = make_float4(xsr[0] - 2.f*acc[0][j], xsr[1] - 2.f*acc[1][j],
                                    xsr[2] - 2.f*acc[2][j], xsr[3] - 2.f*acc[3][j]);
            float4 m1 = make_float4(xsr[4] - 2.f*acc[4][j], xsr[5] - 2.f*acc[5][j],
                                    xsr[6] - 2.f*acc[6][j], xsr[7] - 2.f*acc[7][j]);
            __stcs((float4*)&g_key[base],     m0);
            __stcs((float4*)&g_key[base + 4], m1);
        }
    }
}

// ---------------- kernel C: 2-pass radix + survivor compaction ----------------
// Output SET must equal stable-argsort top-KNN: all keys below theta-bin,
// plus (value, index)-lexicographic smallest within the bin. Order in g_idx
// is irrelevant (gather takes max over the set).
__global__ __launch_bounds__(256) void select_kernel() {
    int row = blockIdx.x;
    int iLocal = row & (NPTS - 1);
    const float4* keys = (const float4*)(g_key + (size_t)row * NPTS);
    int t = threadIdx.x;

    unsigned v[16];
#pragma unroll
    for (int i2 = 0; i2 < 4; i2++) {
        int f4 = t + i2 * 256;
        float4 kv = __ldcs(&keys[f4]);
        float vv[4] = {kv.x, kv.y, kv.z, kv.w};
        int j0 = f4 * 4;
#pragma unroll
        for (int e = 0; e < 4; e++) {
            unsigned u = __float_as_uint(vv[e]);
            u = (u & 0x80000000u) ? ~u : (u | 0x80000000u);
            v[i2 * 4 + e] = (j0 + e == iLocal) ? 0xFFFFFFFFu : u;
        }
    }

    __shared__ int hist[256];
    __shared__ int sD, sCb, sNeed;
    __shared__ int cnt1, cntT;
    __shared__ unsigned tieb[256];

    unsigned prefix = 0, pmask = 0;
    if (t == 0) sNeed = KNN;

    // passes 0,1: bits [31:24], [23:16]
    for (int pass = 0; pass < 2; pass++) {
        int shift = 24 - 8 * pass;
        hist[t] = 0;
        __syncthreads();
#pragma unroll
        for (int q = 0; q < 16; q++) {
            bool ok = (v[q] & pmask) == prefix;
            unsigned act = __ballot_sync(0xffffffffu, ok);
            if (ok) {
                unsigned d = (v[q] >> shift) & 255u;
                unsigned m = __match_any_sync(act, d);
                if ((t & 31) == (__ffs(m) - 1))
                    atomicAdd(&hist[d], __popc(m));
            }
        }
        __syncthreads();
        if (t < 32) {
            int s[8], tot = 0, base = t * 8;
#pragma unroll
            for (int q2 = 0; q2 < 8; q2++) { s[q2] = hist[base + q2]; tot += s[q2]; }
            int inc = tot;
#pragma unroll
            for (int off = 1; off < 32; off <<= 1) {
                int o = __shfl_up_sync(0xffffffffu, inc, off);
                if (t >= off) inc += o;
            }
            int ex = inc - tot;
            int nd = sNeed;
            if (ex < nd && nd <= inc) {
                int run = ex;
#pragma unroll
                for (int q2 = 0; q2 < 8; q2++) {
                    if (nd <= run + s[q2]) { sD = base + q2; sCb = run; break; }
                    run += s[q2];
                }
            }
        }
        __syncthreads();
        prefix |= ((unsigned)sD) << shift;
        pmask  |= 0xFFu << shift;
        if (t == 0) sNeed -= sCb;
    }

    // collect: below-bin -> direct output; in-bin -> packed (low16<<12)|idx
    if (t == 0) { cnt1 = 0; cntT = 0; }
    __syncthreads();
    unsigned thetaHi = prefix >> 16;
    int* outp = g_idx + row * KNN;
#pragma unroll
    for (int q = 0; q < 16; q++) {
        int j = (t + (q >> 2) * 256) * 4 + (q & 3);
        unsigned hi = v[q] >> 16;
        if (hi < thetaHi)       { int s2 = atomicAdd(&cnt1, 1); outp[s2] = j; }
        else if (hi == thetaHi) {
            int s2 = atomicAdd(&cntT, 1);
            if (s2 < 256) tieb[s2] = ((v[q] & 0xFFFFu) << 12) | (unsigned)j;
        }
    }
    __syncthreads();
    int nTie  = cntT;
    int needF = sNeed;   // cnt1 == KNN - needF by construction

    if (nTie <= 256) {
        // fast path: warp 0 iteratively picks needF smallest packed (value,idx)
        if (t < 32) {
            unsigned c[8];
#pragma unroll
            for (int i = 0; i < 8; i++) {
                int ix = t + i * 32;
                c[i] = (ix < nTie) ? tieb[ix] : 0xFFFFFFFFu;
            }
            int c1 = cnt1;
            for (int s2 = 0; s2 < needF; s2++) {
                unsigned m = 0xFFFFFFFFu;
#pragma unroll
                for (int i = 0; i < 8; i++) m = (c[i] < m) ? c[i] : m;
                unsigned r = m;
#pragma unroll
                for (int off = 16; off; off >>= 1) {
                    unsigned o = __shfl_xor_sync(0xffffffffu, r, off);
                    r = (o < r) ? o : r;
                }
                if (t == 0) outp[c1 + s2] = (int)(r & 0xFFFu);
#pragma unroll
                for (int i = 0; i < 8; i++) if (c[i] == r) c[i] = 0xFFFFFFFFu;
            }
        }
    } else {
        // slow path (pathological tie mass): finish passes 2,3 then exact collect
        for (int pass = 2; pass < 4; pass++) {
            int shift = 24 - 8 * pass;
            hist[t] = 0;
            __syncthreads();
#pragma unroll
            for (int q = 0; q < 16; q++) {
                bool ok = (v[q] & pmask) == prefix;
                unsigned act = __ballot_sync(0xffffffffu, ok);
                if (ok) {
                    unsigned d = (v[q] >> shift) & 255u;
                    unsigned m = __match_any_sync(act, d);
                    if ((t & 31) == (__ffs(m) - 1))
                        atomicAdd(&hist[d], __popc(m));
                }
            }
            __syncthreads();
            if (t < 32) {
                int s[8], tot = 0, base = t * 8;
#pragma unroll
                for (int q2 = 0; q2 < 8; q2++) { s[q2] = hist[base + q2]; tot += s[q2]; }
                int inc = tot;
#pragma unroll
                for (int off = 1; off < 32; off <<= 1) {
                    int o = __shfl_up_sync(0xffffffffu, inc, off);
                    if (t >= off) inc += o;
                }
                int ex = inc - tot;
                int nd = sNeed;
                if (ex < nd && nd <= inc) {
                    int run = ex;
#pragma unroll
                    for (int q2 = 0; q2 < 8; q2++) {
                        if (nd <= run + s[q2]) { sD = base + q2; sCb = run; break; }
                        run += s[q2];
                    }
                }
            }
            __syncthreads();
            prefix |= ((unsigned)sD) << shift;
            pmask  |= 0xFFu << shift;
            if (t == 0) sNeed -= sCb;
        }
        if (t == 0) { cnt1 = 0; cntT = 0; }
        __syncthreads();
        unsigned theta = prefix;
#pragma unroll
        for (int q = 0; q < 16; q++) {
            int j = (t + (q >> 2) * 256) * 4 + (q & 3);
            if (v[q] < theta)       { int s2 = atomicAdd(&cnt1, 1); outp[s2] = j; }
            else if (v[q] == theta) { int s2 = atomicAdd(&cntT, 1); if (s2 < 256) tieb[s2] = (unsigned)j; }
        }
        __syncthreads();
        if (t == 0) {
            int nt = cntT < 256 ? cntT : 256;
            int nf = sNeed, c1 = cnt1;
            for (int s2 = 0; s2 < nf; s2++) {
                unsigned bi = 0, bv2 = 0xFFFFFFFFu;
                for (int q = 0; q < nt; q++) if (tieb[q] < bv2) { bv2 = tieb[q]; bi = q; }
                tieb[bi] = 0xFFFFFFFFu;
                outp[c1 + s2] = (int)bv2;
            }
        }
    }
}

// ---------------- kernel D: gather-max epilogue ----------------
__global__ void gather_kernel(float* __restrict__ out) {
    int gid = blockIdx.x * blockDim.x + threadIdx.x;
    int p = gid >> 6;
    int o = gid & 63;
    int bbase = p & ~(NPTS - 1);
    const int* ip = g_idx + p * KNN;
    float m = -3.402823466e38f;
#pragma unroll
    for (int q = 0; q < KNN; q++) {
        int j = ip[q];
        m = fmaxf(m, g_v[(size_t)(bbase + j) * FOUT + o]);
    }
    out[gid] = g_u[gid] + m;
}

// ---------------- launch: simple single-stream sequence ----------------
extern "C" void kernel_launch(void* const* d_in, const int* in_sizes, int n_in,
                              void* d_out, int out_size) {
    const float* x    = (const float*)d_in[0];
    const float* W    = (const float*)d_in[1];
    const float* bias = (const float*)d_in[2];
    float* out = (float*)d_out;

    static bool s_init = false;
    if (!s_init) {
        s_init = true;
        cudaFuncSetAttribute(dist_kernel,
                             cudaFuncAttributeMaxDynamicSharedMemorySize, DIST_SMEM);
    }

    transform_kernel<<<TOTAL / 128, 128>>>(x, W, bias);
    dist_kernel<<<dim3(528, 1, BATCH), 256, DIST_SMEM>>>();
    select_kernel<<<TOTAL, 256>>>();
    gather_kernel<<<(TOTAL * FOUT) / 256, 256>>>(out);
}